// round 12
// baseline (speedup 1.0000x reference)
#include <cuda_runtime.h>
#include <cuda_fp16.h>

#define HH 128
#define WW 128
#define PLANE (HH*WW)
#define CYC 21
#define TW 16
#define TH 8
#define HLW 26              // halo cols: tw0-5 .. tw0+20
#define HLH 13              // halo rows: th0 .. th0+12
#define NC (HLW*HLH)        // 338
#define NT 128              // 64 pixel-pairs x 2 jj-parity groups
#define NBLK 512            // 8*16*4

typedef unsigned long long u64;
typedef unsigned int u32;

__device__ float g_part[NBLK];
__device__ unsigned int g_cnt = 0;

__device__ __forceinline__ u64 pack2(float lo, float hi) {
    u64 r; asm("mov.b64 %0,{%1,%2};" : "=l"(r) : "f"(lo), "f"(hi)); return r;
}
__device__ __forceinline__ void unpack2(u64 v, float& lo, float& hi) {
    asm("mov.b64 {%0,%1},%2;" : "=f"(lo), "=f"(hi) : "l"(v));
}
__device__ __forceinline__ u64 add2(u64 a, u64 b) {
    u64 d; asm("add.rn.f32x2 %0,%1,%2;" : "=l"(d) : "l"(a), "l"(b)); return d;
}
__device__ __forceinline__ u64 mul2(u64 a, u64 b) {
    u64 d; asm("mul.rn.f32x2 %0,%1,%2;" : "=l"(d) : "l"(a), "l"(b)); return d;
}
__device__ __forceinline__ u64 ffma2(u64 a, u64 b, u64 c) {
    u64 d; asm("fma.rn.f32x2 %0,%1,%2,%3;" : "=l"(d) : "l"(a), "l"(b), "l"(c)); return d;
}
__device__ __forceinline__ float ex2(float v) {
    float r; asm("ex2.approx.ftz.f32 %0,%1;" : "=f"(r) : "f"(v)); return r;
}
__device__ __forceinline__ u32 hmul2u(u32 a, u32 b) {
    u32 d; asm("mul.rn.f16x2 %0,%1,%2;" : "=r"(d) : "r"(a), "r"(b)); return d;
}
__device__ __forceinline__ u32 hfma2u(u32 a, u32 b, u32 c) {
    u32 d; asm("fma.rn.f16x2 %0,%1,%2,%3;" : "=r"(d) : "r"(a), "r"(b), "r"(c)); return d;
}
__device__ __forceinline__ u32 hadd2u(u32 a, u32 b) {
    u32 d; asm("add.rn.f16x2 %0,%1,%2;" : "=r"(d) : "r"(a), "r"(b)); return d;
}
__device__ __forceinline__ u32 prmt(u32 a, u32 sel) {
    u32 d; asm("prmt.b32 %0,%1,%1,%2;" : "=r"(d) : "r"(a), "r"(sel)); return d;
}

#define XSCALE 8.493218003f               // sqrt(50*log2(e)); sp = 50*log2e*|dx|^2
#define CXY   (-0.020037431123458f)       // -log2(e)/72

// half-window exy value: 2*exp(-(di^2+dj^2)/72) inside H, else 0
__device__ __forceinline__ float hw_exy(int di, int dj) {
    if (dj >= -5 && dj <= 5 && (di >= 1 || dj >= 1))
        return 2.0f * __expf(-(float)(di * di + dj * dj) * (1.0f / 72.0f));
    return 0.0f;
}

// column parity swizzle: even cols -> [0,13), odd cols -> [13,26)
__device__ __forceinline__ int swz(int c) { return (c & 1) * 13 + (c >> 1); }

__global__ __launch_bounds__(NT, 3) void crf_fused(const float* __restrict__ x,
                                                   const float* __restrict__ y,
                                                   float* __restrict__ out) {
    __shared__ float4 Ash4[NC];       // scaled (x0,x1,x2,0); OOB cells all-zero
    __shared__ uint4  ysh[3 * NC];    // y fp16 half2 pairs; ch21 slot = in-bounds flag (1.0)
    __shared__ float4 TABP[2 * 36];   // per (g, idx): (0.9*t_pc0, 0.9*t_pc1, 0.1*t_pc0, 0.1*t_pc1)
    __shared__ float  red[4];
    __shared__ int    lastflag;

    const int tid = threadIdx.x;
    const int g   = tid >> 6;         // jj parity group
    const int pid = tid & 63;
    const int px  = pid & 7;          // pair col: pixels (2px, 2px+1)
    const int py  = pid >> 3;         // pixel row 0..7
    const int th0 = blockIdx.y * TH, tw0 = blockIdx.x * TW;
    const int bz = blockIdx.z;
    const float* xb = x + (size_t)bz * 3 * PLANE;
    const float* yb = y + (size_t)bz * CYC * PLANE;

    // ---- folded K table ----
    for (int t = tid; t < 72; t += NT) {
        int g2 = t / 36, idx = t - g2 * 36;
        int ii = idx / 6, m = idx - ii * 6;
        float t0 = hw_exy(ii, g2 + 2 * m + 1 - 6);   // pc0 multiplier
        float t1 = hw_exy(ii, g2 + 2 * m - 6);       // pc1 multiplier
        TABP[g2 * 36 + idx] = make_float4(0.9f * t0, 0.9f * t1, 0.1f * t0, 0.1f * t1);
    }

    // ---- halo load: x scaled fp32; y fp16-packed with flag channel; OOB zero ----
    for (int cell = tid; cell < NC; cell += NT) {
        int r = cell / HLW, c = cell - r * HLW;
        int gh = th0 + r, gw = tw0 - 5 + c;
        bool v = (gh < HH) && ((unsigned)gw < WW);
        int gidx = gh * WW + gw;
        int dst = r * HLW + swz(c);
        float4 a = make_float4(0.f, 0.f, 0.f, 0.f);
        if (v) {
            a.x = xb[gidx] * XSCALE;
            a.y = xb[PLANE + gidx] * XSCALE;
            a.z = xb[2 * PLANE + gidx] * XSCALE;
        }
        Ash4[dst] = a;
        #pragma unroll
        for (int cg = 0; cg < 3; ++cg) {
            uint4 q = make_uint4(0u, 0u, 0u, 0u);
            if (v) {
                u32 h[4];
                #pragma unroll
                for (int pq = 0; pq < 4; ++pq) {
                    int ch = cg * 8 + pq * 2;
                    float a0 = (ch < CYC) ? yb[ch * PLANE + gidx] : 0.f;
                    float a1 = (ch + 1 < CYC) ? yb[(ch + 1) * PLANE + gidx]
                                              : ((ch + 1 == CYC) ? 1.0f : 0.f);  // flag in ch21
                    __half2 hh = __floats2half2_rn(a0, a1);
                    h[pq] = *(u32*)&hh;
                }
                q.x = h[0]; q.y = h[1]; q.z = h[2]; q.w = h[3];
            }
            ysh[cg * NC + dst] = q;
        }
    }
    __syncthreads();

    // ---- per-thread centers ----
    const int cc0 = py * HLW + swz(2 * px + 5);
    const int cc1 = py * HLW + swz(2 * px + 6);
    u32 yc0[11], yc1[11];
    {
        uint4 a0 = ysh[cc0], b0 = ysh[NC + cc0], c0 = ysh[2 * NC + cc0];
        yc0[0]=a0.x; yc0[1]=a0.y; yc0[2]=a0.z; yc0[3]=a0.w;
        yc0[4]=b0.x; yc0[5]=b0.y; yc0[6]=b0.z; yc0[7]=b0.w;
        yc0[8]=c0.x; yc0[9]=c0.y; yc0[10]=c0.z;
        uint4 a1 = ysh[cc1], b1 = ysh[NC + cc1], c1 = ysh[2 * NC + cc1];
        yc1[0]=a1.x; yc1[1]=a1.y; yc1[2]=a1.z; yc1[3]=a1.w;
        yc1[4]=b1.x; yc1[5]=b1.y; yc1[6]=b1.z; yc1[7]=b1.w;
        yc1[8]=c1.x; yc1[9]=c1.y; yc1[10]=c1.z;
    }
    // overwrite the center's ch21 flag with -1.0 (half 0xBC00): dot' = <y,y> - 1
    yc0[10] = (yc0[10] & 0x0000FFFFu) | 0xBC000000u;
    yc1[10] = (yc1[10] & 0x0000FFFFu) | 0xBC000000u;

    const float4 xc0 = Ash4[cc0];
    const float4 xc1 = Ash4[cc1];
    const u64 ng0 = pack2(-xc0.x, -xc1.x);
    const u64 ng1 = pack2(-xc0.y, -xc1.y);
    const u64 ng2 = pack2(-xc0.z, -xc1.z);
    const u64 cm1 = pack2(-1.0f, -1.0f);

    // 8 persistent half2 accumulators (cellA/cellB x pixel x chain-half)
    u32 aA0a = 0u, aA0b = 0u, aA1a = 0u, aA1b = 0u;
    u32 aB0a = 0u, aB0b = 0u, aB1a = 0u, aB1b = 0u;
    const float4* tabg = TABP + g * 36;
    const int rbase = py * HLW + g * 13 + px;

    // ---- mainloop: 18 iterations x 2 cells (same row: m=2q, 2q+1) ----
    float4 xvA = Ash4[rbase],       xvB = Ash4[rbase + 1];
    uint4  vA0 = ysh[rbase],        vB0 = ysh[rbase + 1];
    uint4  vA1 = ysh[NC + rbase],   vB1 = ysh[NC + rbase + 1];
    uint4  vA2 = ysh[2*NC + rbase], vB2 = ysh[2*NC + rbase + 1];
    float4 tpA = tabg[0],           tpB = tabg[1];

    #pragma unroll
    for (int k = 0; k < 18; ++k) {
        const float4 cxA = xvA, cxB = xvB;
        const uint4 cA0 = vA0, cA1 = vA1, cA2 = vA2;
        const uint4 cB0 = vB0, cB1 = vB1, cB2 = vB2;
        const float4 ctA = tpA, ctB = tpB;
        if (k < 17) {
            const int kn = k + 1;
            const int cell = rbase + (kn / 3) * HLW + 2 * (kn % 3);
            xvA = Ash4[cell];       xvB = Ash4[cell + 1];
            vA0 = ysh[cell];        vB0 = ysh[cell + 1];
            vA1 = ysh[NC + cell];   vB1 = ysh[NC + cell + 1];
            vA2 = ysh[2*NC + cell]; vB2 = ysh[2*NC + cell + 1];
            tpA = tabg[2 * kn];     tpB = tabg[2 * kn + 1];
        }

        // K paths for both cells (independent)
        u64 dA0 = add2(pack2(cxA.x, cxA.x), ng0);
        u64 dA1 = add2(pack2(cxA.y, cxA.y), ng1);
        u64 dA2 = add2(pack2(cxA.z, cxA.z), ng2);
        u64 dB0 = add2(pack2(cxB.x, cxB.x), ng0);
        u64 dB1 = add2(pack2(cxB.y, cxB.y), ng1);
        u64 dB2 = add2(pack2(cxB.z, cxB.z), ng2);
        u64 sA = mul2(dA0, dA0); sA = ffma2(dA1, dA1, sA); sA = ffma2(dA2, dA2, sA);
        u64 sB = mul2(dB0, dB0); sB = ffma2(dB1, dB1, sB); sB = ffma2(dB2, dB2, sB);
        sA = mul2(sA, cm1); sB = mul2(sB, cm1);
        float nsA0, nsA1, nsB0, nsB1;
        unpack2(sA, nsA0, nsA1); unpack2(sB, nsB0, nsB1);
        const float EA0 = ex2(nsA0), EA1 = ex2(nsA1);
        const float EB0 = ex2(nsB0), EB1 = ex2(nsB1);
        const float KA0 = fmaf(EA0, ctA.x, ctA.z);
        const float KA1 = fmaf(EA1, ctA.y, ctA.w);
        const float KB0 = fmaf(EB0, ctB.x, ctB.z);
        const float KB1 = fmaf(EB1, ctB.y, ctB.w);
        __half2 khA = __floats2half2_rn(KA0, KA1);
        __half2 khB = __floats2half2_rn(KB0, KB1);
        const u32 KpA = *(u32*)&khA, KpB = *(u32*)&khB;
        const u32 KA0d = prmt(KpA, 0x1010u), KA1d = prmt(KpA, 0x3232u);
        const u32 KB0d = prmt(KpB, 0x1010u), KB1d = prmt(KpB, 0x3232u);

        // 8 independent dot' chains (cell x pixel x half), depth 5-6
        u32 pA0a = hmul2u(cA0.x, yc0[0]);
        u32 pA1a = hmul2u(cA0.x, yc1[0]);
        u32 pA0b = hmul2u(cA1.z, yc0[6]);
        u32 pA1b = hmul2u(cA1.z, yc1[6]);
        u32 pB0a = hmul2u(cB0.x, yc0[0]);
        u32 pB1a = hmul2u(cB0.x, yc1[0]);
        u32 pB0b = hmul2u(cB1.z, yc0[6]);
        u32 pB1b = hmul2u(cB1.z, yc1[6]);
        pA0a = hfma2u(cA0.y, yc0[1], pA0a);  pA1a = hfma2u(cA0.y, yc1[1], pA1a);
        pB0a = hfma2u(cB0.y, yc0[1], pB0a);  pB1a = hfma2u(cB0.y, yc1[1], pB1a);
        pA0b = hfma2u(cA1.w, yc0[7], pA0b);  pA1b = hfma2u(cA1.w, yc1[7], pA1b);
        pB0b = hfma2u(cB1.w, yc0[7], pB0b);  pB1b = hfma2u(cB1.w, yc1[7], pB1b);
        pA0a = hfma2u(cA0.z, yc0[2], pA0a);  pA1a = hfma2u(cA0.z, yc1[2], pA1a);
        pB0a = hfma2u(cB0.z, yc0[2], pB0a);  pB1a = hfma2u(cB0.z, yc1[2], pB1a);
        pA0b = hfma2u(cA2.x, yc0[8], pA0b);  pA1b = hfma2u(cA2.x, yc1[8], pA1b);
        pB0b = hfma2u(cB2.x, yc0[8], pB0b);  pB1b = hfma2u(cB2.x, yc1[8], pB1b);
        pA0a = hfma2u(cA0.w, yc0[3], pA0a);  pA1a = hfma2u(cA0.w, yc1[3], pA1a);
        pB0a = hfma2u(cB0.w, yc0[3], pB0a);  pB1a = hfma2u(cB0.w, yc1[3], pB1a);
        pA0b = hfma2u(cA2.y, yc0[9], pA0b);  pA1b = hfma2u(cA2.y, yc1[9], pA1b);
        pB0b = hfma2u(cB2.y, yc0[9], pB0b);  pB1b = hfma2u(cB2.y, yc1[9], pB1b);
        pA0a = hfma2u(cA1.x, yc0[4], pA0a);  pA1a = hfma2u(cA1.x, yc1[4], pA1a);
        pB0a = hfma2u(cB1.x, yc0[4], pB0a);  pB1a = hfma2u(cB1.x, yc1[4], pB1a);
        pA0b = hfma2u(cA2.z, yc0[10], pA0b); pA1b = hfma2u(cA2.z, yc1[10], pA1b);
        pB0b = hfma2u(cB2.z, yc0[10], pB0b); pB1b = hfma2u(cB2.z, yc1[10], pB1b);
        pA0a = hfma2u(cA1.y, yc0[5], pA0a);  pA1a = hfma2u(cA1.y, yc1[5], pA1a);
        pB0a = hfma2u(cB1.y, yc0[5], pB0a);  pB1a = hfma2u(cB1.y, yc1[5], pB1a);

        // accumulate: no per-cell merge, 8 persistent accumulators
        aA0a = hfma2u(KA0d, pA0a, aA0a);  aA0b = hfma2u(KA0d, pA0b, aA0b);
        aA1a = hfma2u(KA1d, pA1a, aA1a);  aA1b = hfma2u(KA1d, pA1b, aA1b);
        aB0a = hfma2u(KB0d, pB0a, aB0a);  aB0b = hfma2u(KB0d, pB0b, aB0b);
        aB1a = hfma2u(KB1d, pB1a, aB1a);  aB1b = hfma2u(KB1d, pB1b, aB1b);
    }

    // ---- epilogue: part = -sum(K*dot') + true-OOB closed form ----
    float acc2 = 0.0f;
    {
        const u32 m0 = hadd2u(hadd2u(aA0a, aA0b), hadd2u(aB0a, aB0b));
        const u32 m1 = hadd2u(hadd2u(aA1a, aA1b), hadd2u(aB1a, aB1b));
        __half2 a = *(__half2*)&m0;
        __half2 b = *(__half2*)&m1;
        acc2 = (__low2float(a) + __high2float(a)) + (__low2float(b) + __high2float(b));
    }
    float acc1 = 0.0f;
    if (g == 0) {
        const int h = th0 + py;
        const int rv = min(5, 127 - h) + min(5, h) + 1;
        #pragma unroll
        for (int pc = 0; pc < 2; ++pc) {
            const int w = tw0 + 2 * px + pc;
            const int cv = min(5, 127 - w) + min(5, w) + 1;
            const int noob = 121 - rv * cv;
            if (noob > 0) {
                const float4 xc = pc ? xc1 : xc0;
                const float sxs = xc.x * xc.x + xc.y * xc.y + xc.z * xc.z;  // scaled
                const float F = fmaf(0.9f, ex2(-sxs), 0.1f);
                acc1 += (float)noob * ex2((float)(h * h + w * w) * CXY) * F;
            }
        }
    }

    // ---- block reduction + fused final reduction (deterministic) ----
    float part = acc1 - acc2;
    #pragma unroll
    for (int o = 16; o > 0; o >>= 1) part += __shfl_xor_sync(0xffffffffu, part, o);
    const int warp = tid >> 5, lane = tid & 31;
    if (lane == 0) red[warp] = part;
    __syncthreads();
    const int bid = ((bz * gridDim.y) + blockIdx.y) * gridDim.x + blockIdx.x;
    if (tid == 0) {
        g_part[bid] = (red[0] + red[1]) + (red[2] + red[3]);
        __threadfence();
        unsigned old = atomicAdd(&g_cnt, 1u);
        lastflag = (old == NBLK - 1) ? 1 : 0;
    }
    __syncthreads();
    if (lastflag) {
        float v = (g_part[tid] + g_part[tid + 128]) +
                  (g_part[tid + 256] + g_part[tid + 384]);
        #pragma unroll
        for (int o = 16; o > 0; o >>= 1) v += __shfl_xor_sync(0xffffffffu, v, o);
        if (lane == 0) red[warp] = v;
        __syncthreads();
        if (tid == 0) {
            out[0] = ((red[0] + red[1]) + (red[2] + red[3])) * (1.0f / 65536.0f);
            g_cnt = 0;
        }
    }
}

extern "C" void kernel_launch(void* const* d_in, const int* in_sizes, int n_in,
                              void* d_out, int out_size) {
    const float* x = (const float*)d_in[0];
    const float* y = (const float*)d_in[1];
    (void)in_sizes; (void)n_in; (void)out_size;
    dim3 grid(WW / TW, HH / TH, 4);
    crf_fused<<<grid, NT>>>(x, y, (float*)d_out);
}

// round 13
// speedup vs baseline: 1.0381x; 1.0381x over previous
#include <cuda_runtime.h>
#include <cuda_fp16.h>

#define HH 128
#define WW 128
#define PLANE (HH*WW)
#define CYC 21
#define TW 16
#define TH 8
#define HLW 26              // halo cols: tw0-5 .. tw0+20
#define HLH 13              // halo rows: th0 .. th0+12
#define NC (HLW*HLH)        // 338
#define NT 128              // 64 pixel-pairs x 2 jj-parity groups
#define NBLK 512            // 8*16*4

typedef unsigned long long u64;
typedef unsigned int u32;

__device__ float g_part[NBLK];
__device__ unsigned int g_cnt = 0;

__device__ __forceinline__ u64 pack2(float lo, float hi) {
    u64 r; asm("mov.b64 %0,{%1,%2};" : "=l"(r) : "f"(lo), "f"(hi)); return r;
}
__device__ __forceinline__ void unpack2(u64 v, float& lo, float& hi) {
    asm("mov.b64 {%0,%1},%2;" : "=f"(lo), "=f"(hi) : "l"(v));
}
__device__ __forceinline__ u64 add2(u64 a, u64 b) {
    u64 d; asm("add.rn.f32x2 %0,%1,%2;" : "=l"(d) : "l"(a), "l"(b)); return d;
}
__device__ __forceinline__ u64 mul2(u64 a, u64 b) {
    u64 d; asm("mul.rn.f32x2 %0,%1,%2;" : "=l"(d) : "l"(a), "l"(b)); return d;
}
__device__ __forceinline__ u64 ffma2(u64 a, u64 b, u64 c) {
    u64 d; asm("fma.rn.f32x2 %0,%1,%2,%3;" : "=l"(d) : "l"(a), "l"(b), "l"(c)); return d;
}
__device__ __forceinline__ float ex2(float v) {
    float r; asm("ex2.approx.ftz.f32 %0,%1;" : "=f"(r) : "f"(v)); return r;
}
__device__ __forceinline__ u32 hex2(u32 a) {
    u32 d; asm("ex2.approx.f16x2 %0,%1;" : "=r"(d) : "r"(a)); return d;
}
__device__ __forceinline__ u32 hmul2u(u32 a, u32 b) {
    u32 d; asm("mul.rn.f16x2 %0,%1,%2;" : "=r"(d) : "r"(a), "r"(b)); return d;
}
__device__ __forceinline__ u32 hfma2u(u32 a, u32 b, u32 c) {
    u32 d; asm("fma.rn.f16x2 %0,%1,%2,%3;" : "=r"(d) : "r"(a), "r"(b), "r"(c)); return d;
}
__device__ __forceinline__ u32 hadd2u(u32 a, u32 b) {
    u32 d; asm("add.rn.f16x2 %0,%1,%2;" : "=r"(d) : "r"(a), "r"(b)); return d;
}
__device__ __forceinline__ u32 prmt(u32 a, u32 sel) {
    u32 d; asm("prmt.b32 %0,%1,%1,%2;" : "=r"(d) : "r"(a), "r"(sel)); return d;
}

#define XSCALE 8.493218003f               // sqrt(50*log2(e)); s = 50*log2e*|dx|^2
#define CXY   (-0.020037431123458f)       // -log2(e)/72

// half-window exy value: 2*exp(-(di^2+dj^2)/72) inside H, else 0
__device__ __forceinline__ float hw_exy(int di, int dj) {
    if (dj >= -5 && dj <= 5 && (di >= 1 || dj >= 1))
        return 2.0f * __expf(-(float)(di * di + dj * dj) * (1.0f / 72.0f));
    return 0.0f;
}

// column parity swizzle: even cols -> [0,13), odd cols -> [13,26)
__device__ __forceinline__ int swz(int c) { return (c & 1) * 13 + (c >> 1); }

__global__ __launch_bounds__(NT, 4) void crf_fused(const float* __restrict__ x,
                                                   const float* __restrict__ y,
                                                   float* __restrict__ out) {
    __shared__ float4 Ash4[NC];       // scaled (x0,x1,x2,0); OOB cells all-zero
    __shared__ uint4  ysh[3 * NC];    // y fp16 half2 pairs; ch21 slot = in-bounds flag (1.0)
    __shared__ uint2  TABH[2 * 18 * 2]; // [g][k][pc]: (h2(t9A,t9B), h2(t1A,t1B))
    __shared__ float  red[4];
    __shared__ int    lastflag;

    const int tid = threadIdx.x;
    const int g   = tid >> 6;         // jj parity group
    const int pid = tid & 63;
    const int px  = pid & 7;          // pair col: pixels (2px, 2px+1)
    const int py  = pid >> 3;         // pixel row 0..7
    const int th0 = blockIdx.y * TH, tw0 = blockIdx.x * TW;
    const int bz = blockIdx.z;
    const float* xb = x + (size_t)bz * 3 * PLANE;
    const float* yb = y + (size_t)bz * CYC * PLANE;

    // ---- folded half2 K table ----
    // iter k: row ii = k/3, cell pair m = 2*(k%3), 2*(k%3)+1; jj = g + 2m
    // pc0: dj = jj - 5; pc1: dj = jj - 6
    for (int t = tid; t < 72; t += NT) {
        int g2 = t / 36, rem = t - g2 * 36;
        int k = rem / 2, pc = rem & 1;
        int ii = k / 3, q = k - 3 * (k / 3);
        int mA = 2 * q, mB = 2 * q + 1;
        int djA = g2 + 2 * mA - 5 - pc;
        int djB = g2 + 2 * mB - 5 - pc;
        float tA = hw_exy(ii, djA), tB = hw_exy(ii, djB);
        __half2 h9 = __floats2half2_rn(0.9f * tA, 0.9f * tB);
        __half2 h1 = __floats2half2_rn(0.1f * tA, 0.1f * tB);
        TABH[t] = make_uint2(*(u32*)&h9, *(u32*)&h1);
    }

    // ---- halo load: x scaled fp32; y fp16-packed with flag channel; OOB zero ----
    for (int cell = tid; cell < NC; cell += NT) {
        int r = cell / HLW, c = cell - r * HLW;
        int gh = th0 + r, gw = tw0 - 5 + c;
        bool v = (gh < HH) && ((unsigned)gw < WW);
        int gidx = gh * WW + gw;
        int dst = r * HLW + swz(c);
        float4 a = make_float4(0.f, 0.f, 0.f, 0.f);
        if (v) {
            a.x = xb[gidx] * XSCALE;
            a.y = xb[PLANE + gidx] * XSCALE;
            a.z = xb[2 * PLANE + gidx] * XSCALE;
        }
        Ash4[dst] = a;
        #pragma unroll
        for (int cg = 0; cg < 3; ++cg) {
            uint4 q = make_uint4(0u, 0u, 0u, 0u);
            if (v) {
                u32 h[4];
                #pragma unroll
                for (int pq = 0; pq < 4; ++pq) {
                    int ch = cg * 8 + pq * 2;
                    float a0 = (ch < CYC) ? yb[ch * PLANE + gidx] : 0.f;
                    float a1 = (ch + 1 < CYC) ? yb[(ch + 1) * PLANE + gidx]
                                              : ((ch + 1 == CYC) ? 1.0f : 0.f);  // flag in ch21
                    __half2 hh = __floats2half2_rn(a0, a1);
                    h[pq] = *(u32*)&hh;
                }
                q.x = h[0]; q.y = h[1]; q.z = h[2]; q.w = h[3];
            }
            ysh[cg * NC + dst] = q;
        }
    }
    __syncthreads();

    // ---- per-thread centers ----
    const int cc0 = py * HLW + swz(2 * px + 5);
    const int cc1 = py * HLW + swz(2 * px + 6);
    u32 yc0[11], yc1[11];
    {
        uint4 a0 = ysh[cc0], b0 = ysh[NC + cc0], c0 = ysh[2 * NC + cc0];
        yc0[0]=a0.x; yc0[1]=a0.y; yc0[2]=a0.z; yc0[3]=a0.w;
        yc0[4]=b0.x; yc0[5]=b0.y; yc0[6]=b0.z; yc0[7]=b0.w;
        yc0[8]=c0.x; yc0[9]=c0.y; yc0[10]=c0.z;
        uint4 a1 = ysh[cc1], b1 = ysh[NC + cc1], c1 = ysh[2 * NC + cc1];
        yc1[0]=a1.x; yc1[1]=a1.y; yc1[2]=a1.z; yc1[3]=a1.w;
        yc1[4]=b1.x; yc1[5]=b1.y; yc1[6]=b1.z; yc1[7]=b1.w;
        yc1[8]=c1.x; yc1[9]=c1.y; yc1[10]=c1.z;
    }
    // overwrite the center's ch21 flag with -1.0 (half 0xBC00): dot' = <y,y> - 1
    yc0[10] = (yc0[10] & 0x0000FFFFu) | 0xBC000000u;
    yc1[10] = (yc1[10] & 0x0000FFFFu) | 0xBC000000u;

    const float4 xc0 = Ash4[cc0];
    const float4 xc1 = Ash4[cc1];
    // per-pixel duplicated negated centers (lanes = cells)
    const u64 ngd0_0 = pack2(-xc0.x, -xc0.x), ngd0_1 = pack2(-xc0.y, -xc0.y), ngd0_2 = pack2(-xc0.z, -xc0.z);
    const u64 ngd1_0 = pack2(-xc1.x, -xc1.x), ngd1_1 = pack2(-xc1.y, -xc1.y), ngd1_2 = pack2(-xc1.z, -xc1.z);
    const u64 cm1 = pack2(-1.0f, -1.0f);

    u32 accP0 = 0u, accP1 = 0u;       // half2 accumulators of K*dot'
    const uint2* tabg = TABH + g * 36;
    const int rbase = py * HLW + g * 13 + px;

    // ---- software-pipelined mainloop: 18 iterations x 2 cells (m=2q, 2q+1) ----
    float4 xvA = Ash4[rbase],       xvB = Ash4[rbase + 1];
    uint4  vA0 = ysh[rbase],        vB0 = ysh[rbase + 1];
    uint4  vA1 = ysh[NC + rbase],   vB1 = ysh[NC + rbase + 1];
    uint4  vA2 = ysh[2*NC + rbase], vB2 = ysh[2*NC + rbase + 1];
    uint2  tp0 = tabg[0],           tp1 = tabg[1];

    #pragma unroll
    for (int k = 0; k < 18; ++k) {
        const float4 cxA = xvA, cxB = xvB;
        const uint4 cA0 = vA0, cA1 = vA1, cA2 = vA2;
        const uint4 cB0 = vB0, cB1 = vB1, cB2 = vB2;
        const uint2 ct0 = tp0, ct1 = tp1;
        if (k < 17) {
            const int kn = k + 1;
            const int cell = rbase + (kn / 3) * HLW + 2 * (kn % 3);
            xvA = Ash4[cell];       xvB = Ash4[cell + 1];
            vA0 = ysh[cell];        vB0 = ysh[cell + 1];
            vA1 = ysh[NC + cell];   vB1 = ysh[NC + cell + 1];
            vA2 = ysh[2*NC + cell]; vB2 = ysh[2*NC + cell + 1];
            tp0 = tabg[2 * kn];     tp1 = tabg[2 * kn + 1];
        }

        // lanes = (cellA, cellB)
        const u64 p0 = pack2(cxA.x, cxB.x);
        const u64 p1 = pack2(cxA.y, cxB.y);
        const u64 p2 = pack2(cxA.z, cxB.z);

        // pixel 0: s packed over cells, then fp16 exp + K-combine
        u32 K0;
        {
            u64 d0 = add2(p0, ngd0_0), d1 = add2(p1, ngd0_1), d2 = add2(p2, ngd0_2);
            u64 s = mul2(d0, d0); s = ffma2(d1, d1, s); s = ffma2(d2, d2, s);
            s = mul2(s, cm1);
            float nsA, nsB; unpack2(s, nsA, nsB);
            __half2 nh = __floats2half2_rn(nsA, nsB);      // lo = A
            const u32 E = hex2(*(u32*)&nh);                // (2^-sA, 2^-sB)
            K0 = hfma2u(E, ct0.x, ct0.y);                  // (K0A, K0B)
        }
        // pixel 1
        u32 K1;
        {
            u64 d0 = add2(p0, ngd1_0), d1 = add2(p1, ngd1_1), d2 = add2(p2, ngd1_2);
            u64 s = mul2(d0, d0); s = ffma2(d1, d1, s); s = ffma2(d2, d2, s);
            s = mul2(s, cm1);
            float nsA, nsB; unpack2(s, nsA, nsB);
            __half2 nh = __floats2half2_rn(nsA, nsB);
            const u32 E = hex2(*(u32*)&nh);
            K1 = hfma2u(E, ct1.x, ct1.y);                  // (K1A, K1B)
        }
        const u32 K0A = prmt(K0, 0x1010u), K0B = prmt(K0, 0x3232u);
        const u32 K1A = prmt(K1, 0x1010u), K1B = prmt(K1, 0x3232u);

        // dot' chains: per (cell, pixel), 11 half2 terms split 6+5
        u32 pA0a = hmul2u(cA0.x, yc0[0]);
        u32 pA1a = hmul2u(cA0.x, yc1[0]);
        u32 pA0b = hmul2u(cA1.z, yc0[6]);
        u32 pA1b = hmul2u(cA1.z, yc1[6]);
        u32 pB0a = hmul2u(cB0.x, yc0[0]);
        u32 pB1a = hmul2u(cB0.x, yc1[0]);
        u32 pB0b = hmul2u(cB1.z, yc0[6]);
        u32 pB1b = hmul2u(cB1.z, yc1[6]);
        pA0a = hfma2u(cA0.y, yc0[1], pA0a);  pA1a = hfma2u(cA0.y, yc1[1], pA1a);
        pB0a = hfma2u(cB0.y, yc0[1], pB0a);  pB1a = hfma2u(cB0.y, yc1[1], pB1a);
        pA0b = hfma2u(cA1.w, yc0[7], pA0b);  pA1b = hfma2u(cA1.w, yc1[7], pA1b);
        pB0b = hfma2u(cB1.w, yc0[7], pB0b);  pB1b = hfma2u(cB1.w, yc1[7], pB1b);
        pA0a = hfma2u(cA0.z, yc0[2], pA0a);  pA1a = hfma2u(cA0.z, yc1[2], pA1a);
        pB0a = hfma2u(cB0.z, yc0[2], pB0a);  pB1a = hfma2u(cB0.z, yc1[2], pB1a);
        pA0b = hfma2u(cA2.x, yc0[8], pA0b);  pA1b = hfma2u(cA2.x, yc1[8], pA1b);
        pB0b = hfma2u(cB2.x, yc0[8], pB0b);  pB1b = hfma2u(cB2.x, yc1[8], pB1b);
        pA0a = hfma2u(cA0.w, yc0[3], pA0a);  pA1a = hfma2u(cA0.w, yc1[3], pA1a);
        pB0a = hfma2u(cB0.w, yc0[3], pB0a);  pB1a = hfma2u(cB0.w, yc1[3], pB1a);
        pA0b = hfma2u(cA2.y, yc0[9], pA0b);  pA1b = hfma2u(cA2.y, yc1[9], pA1b);
        pB0b = hfma2u(cB2.y, yc0[9], pB0b);  pB1b = hfma2u(cB2.y, yc1[9], pB1b);
        pA0a = hfma2u(cA1.x, yc0[4], pA0a);  pA1a = hfma2u(cA1.x, yc1[4], pA1a);
        pB0a = hfma2u(cB1.x, yc0[4], pB0a);  pB1a = hfma2u(cB1.x, yc1[4], pB1a);
        pA0b = hfma2u(cA2.z, yc0[10], pA0b); pA1b = hfma2u(cA2.z, yc1[10], pA1b);
        pB0b = hfma2u(cB2.z, yc0[10], pB0b); pB1b = hfma2u(cB2.z, yc1[10], pB1b);
        pA0a = hfma2u(cA1.y, yc0[5], pA0a);  pA1a = hfma2u(cA1.y, yc1[5], pA1a);
        pB0a = hfma2u(cB1.y, yc0[5], pB0a);  pB1a = hfma2u(cB1.y, yc1[5], pB1a);

        const u32 dA0 = hadd2u(pA0a, pA0b);
        const u32 dA1 = hadd2u(pA1a, pA1b);
        const u32 dB0 = hadd2u(pB0a, pB0b);
        const u32 dB1 = hadd2u(pB1a, pB1b);

        accP0 = hfma2u(K0A, dA0, accP0);
        accP0 = hfma2u(K0B, dB0, accP0);
        accP1 = hfma2u(K1A, dA1, accP1);
        accP1 = hfma2u(K1B, dB1, accP1);
    }

    // ---- epilogue: part = -sum(K*dot') + true-OOB closed form ----
    float acc2;
    {
        __half2 a = *(__half2*)&accP0;
        __half2 b = *(__half2*)&accP1;
        acc2 = (__low2float(a) + __high2float(a)) + (__low2float(b) + __high2float(b));
    }
    float acc1 = 0.0f;
    if (g == 0) {
        const int h = th0 + py;
        const int rv = min(5, 127 - h) + min(5, h) + 1;
        #pragma unroll
        for (int pc = 0; pc < 2; ++pc) {
            const int w = tw0 + 2 * px + pc;
            const int cv = min(5, 127 - w) + min(5, w) + 1;
            const int noob = 121 - rv * cv;
            if (noob > 0) {
                const float4 xc = pc ? xc1 : xc0;
                const float sxs = xc.x * xc.x + xc.y * xc.y + xc.z * xc.z;  // scaled
                const float F = fmaf(0.9f, ex2(-sxs), 0.1f);
                acc1 += (float)noob * ex2((float)(h * h + w * w) * CXY) * F;
            }
        }
    }

    // ---- block reduction + fused final reduction (deterministic) ----
    float part = acc1 - acc2;
    #pragma unroll
    for (int o = 16; o > 0; o >>= 1) part += __shfl_xor_sync(0xffffffffu, part, o);
    const int warp = tid >> 5, lane = tid & 31;
    if (lane == 0) red[warp] = part;
    __syncthreads();
    const int bid = ((bz * gridDim.y) + blockIdx.y) * gridDim.x + blockIdx.x;
    if (tid == 0) {
        g_part[bid] = (red[0] + red[1]) + (red[2] + red[3]);
        __threadfence();
        unsigned old = atomicAdd(&g_cnt, 1u);
        lastflag = (old == NBLK - 1) ? 1 : 0;
    }
    __syncthreads();
    if (lastflag) {
        float v = (g_part[tid] + g_part[tid + 128]) +
                  (g_part[tid + 256] + g_part[tid + 384]);
        #pragma unroll
        for (int o = 16; o > 0; o >>= 1) v += __shfl_xor_sync(0xffffffffu, v, o);
        if (lane == 0) red[warp] = v;
        __syncthreads();
        if (tid == 0) {
            out[0] = ((red[0] + red[1]) + (red[2] + red[3])) * (1.0f / 65536.0f);
            g_cnt = 0;
        }
    }
}

extern "C" void kernel_launch(void* const* d_in, const int* in_sizes, int n_in,
                              void* d_out, int out_size) {
    const float* x = (const float*)d_in[0];
    const float* y = (const float*)d_in[1];
    (void)in_sizes; (void)n_in; (void)out_size;
    dim3 grid(WW / TW, HH / TH, 4);
    crf_fused<<<grid, NT>>>(x, y, (float*)d_out);
}

// round 14
// speedup vs baseline: 1.0582x; 1.0194x over previous
#include <cuda_runtime.h>
#include <cuda_fp16.h>

#define HH 128
#define WW 128
#define PLANE (HH*WW)
#define CYC 21
#define TW 16
#define TH 8
#define HLW 26              // halo cols: tw0-5 .. tw0+20
#define HLH 13              // halo rows: th0 .. th0+12
#define NC (HLW*HLH)        // 338
#define NT 128              // 64 pixel-pairs x 2 jj-parity groups
#define NBLK 512            // 8*16*4

typedef unsigned long long u64;
typedef unsigned int u32;

__device__ float g_part[NBLK];
__device__ unsigned int g_cnt = 0;

__device__ __forceinline__ u64 pack2(float lo, float hi) {
    u64 r; asm("mov.b64 %0,{%1,%2};" : "=l"(r) : "f"(lo), "f"(hi)); return r;
}
__device__ __forceinline__ void unpack2(u64 v, float& lo, float& hi) {
    asm("mov.b64 {%0,%1},%2;" : "=f"(lo), "=f"(hi) : "l"(v));
}
__device__ __forceinline__ u64 add2(u64 a, u64 b) {
    u64 d; asm("add.rn.f32x2 %0,%1,%2;" : "=l"(d) : "l"(a), "l"(b)); return d;
}
__device__ __forceinline__ u64 mul2(u64 a, u64 b) {
    u64 d; asm("mul.rn.f32x2 %0,%1,%2;" : "=l"(d) : "l"(a), "l"(b)); return d;
}
__device__ __forceinline__ u64 ffma2(u64 a, u64 b, u64 c) {
    u64 d; asm("fma.rn.f32x2 %0,%1,%2,%3;" : "=l"(d) : "l"(a), "l"(b), "l"(c)); return d;
}
__device__ __forceinline__ float ex2(float v) {
    float r; asm("ex2.approx.ftz.f32 %0,%1;" : "=f"(r) : "f"(v)); return r;
}
__device__ __forceinline__ u32 hex2(u32 a) {
    u32 d; asm("ex2.approx.f16x2 %0,%1;" : "=r"(d) : "r"(a)); return d;
}
__device__ __forceinline__ u32 hmul2u(u32 a, u32 b) {
    u32 d; asm("mul.rn.f16x2 %0,%1,%2;" : "=r"(d) : "r"(a), "r"(b)); return d;
}
__device__ __forceinline__ u32 hfma2u(u32 a, u32 b, u32 c) {
    u32 d; asm("fma.rn.f16x2 %0,%1,%2,%3;" : "=r"(d) : "r"(a), "r"(b), "r"(c)); return d;
}
__device__ __forceinline__ u32 hadd2u(u32 a, u32 b) {
    u32 d; asm("add.rn.f16x2 %0,%1,%2;" : "=r"(d) : "r"(a), "r"(b)); return d;
}
__device__ __forceinline__ u32 prmt(u32 a, u32 sel) {
    u32 d; asm("prmt.b32 %0,%1,%1,%2;" : "=r"(d) : "r"(a), "r"(sel)); return d;
}

#define XSCALE 8.493218003f               // sqrt(50*log2(e)); sp = 50*log2e*|dx|^2
#define CXY   (-0.020037431123458f)       // -log2(e)/72
#define SGN2  0x80008000u                 // fp16x2 sign flip

// half-window exy value: 2*exp(-(di^2+dj^2)/72) inside H, else 0
__device__ __forceinline__ float hw_exy(int di, int dj) {
    if (dj >= -5 && dj <= 5 && (di >= 1 || dj >= 1))
        return 2.0f * __expf(-(float)(di * di + dj * dj) * (1.0f / 72.0f));
    return 0.0f;
}

// column parity swizzle: even cols -> [0,13), odd cols -> [13,26)
__device__ __forceinline__ int swz(int c) { return (c & 1) * 13 + (c >> 1); }

__global__ __launch_bounds__(NT, 4) void crf_fused(const float* __restrict__ x,
                                                   const float* __restrict__ y,
                                                   float* __restrict__ out) {
    __shared__ float4 Ash4[NC];       // scaled (x0,x1,x2,0); OOB cells all-zero
    __shared__ uint4  ysh[3 * NC];    // y fp16 half2 pairs; ch21 slot = in-bounds flag (1.0)
    __shared__ uint2  TABH[2 * 36];   // per (g, idx): (h2(0.9t0,0.9t1), h2(0.1t0,0.1t1))
    __shared__ float  red[4];
    __shared__ int    lastflag;

    const int tid = threadIdx.x;
    const int g   = tid >> 6;         // jj parity group
    const int pid = tid & 63;
    const int px  = pid & 7;          // pair col: pixels (2px, 2px+1)
    const int py  = pid >> 3;         // pixel row 0..7
    const int th0 = blockIdx.y * TH, tw0 = blockIdx.x * TW;
    const int bz = blockIdx.z;
    const float* xb = x + (size_t)bz * 3 * PLANE;
    const float* yb = y + (size_t)bz * CYC * PLANE;

    // ---- folded half2 K table ----
    for (int t = tid; t < 72; t += NT) {
        int g2 = t / 36, idx = t - g2 * 36;
        int ii = idx / 6, m = idx - ii * 6;
        float t0 = hw_exy(ii, g2 + 2 * m + 1 - 6);   // pc0 multiplier
        float t1 = hw_exy(ii, g2 + 2 * m - 6);       // pc1 multiplier
        __half2 h9 = __floats2half2_rn(0.9f * t0, 0.9f * t1);
        __half2 h1 = __floats2half2_rn(0.1f * t0, 0.1f * t1);
        TABH[g2 * 36 + idx] = make_uint2(*(u32*)&h9, *(u32*)&h1);
    }

    // ---- halo load: x scaled fp32; y fp16-packed with flag channel; OOB zero ----
    for (int cell = tid; cell < NC; cell += NT) {
        int r = cell / HLW, c = cell - r * HLW;
        int gh = th0 + r, gw = tw0 - 5 + c;
        bool v = (gh < HH) && ((unsigned)gw < WW);
        int gidx = gh * WW + gw;
        int dst = r * HLW + swz(c);
        float4 a = make_float4(0.f, 0.f, 0.f, 0.f);
        if (v) {
            a.x = xb[gidx] * XSCALE;
            a.y = xb[PLANE + gidx] * XSCALE;
            a.z = xb[2 * PLANE + gidx] * XSCALE;
        }
        Ash4[dst] = a;
        #pragma unroll
        for (int cg = 0; cg < 3; ++cg) {
            uint4 q = make_uint4(0u, 0u, 0u, 0u);
            if (v) {
                u32 h[4];
                #pragma unroll
                for (int pq = 0; pq < 4; ++pq) {
                    int ch = cg * 8 + pq * 2;
                    float a0 = (ch < CYC) ? yb[ch * PLANE + gidx] : 0.f;
                    float a1 = (ch + 1 < CYC) ? yb[(ch + 1) * PLANE + gidx]
                                              : ((ch + 1 == CYC) ? 1.0f : 0.f);  // flag in ch21
                    __half2 hh = __floats2half2_rn(a0, a1);
                    h[pq] = *(u32*)&hh;
                }
                q.x = h[0]; q.y = h[1]; q.z = h[2]; q.w = h[3];
            }
            ysh[cg * NC + dst] = q;
        }
    }
    __syncthreads();

    // ---- per-thread centers ----
    const int cc0 = py * HLW + swz(2 * px + 5);
    const int cc1 = py * HLW + swz(2 * px + 6);
    u32 yc0[11], yc1[11];
    {
        uint4 a0 = ysh[cc0], b0 = ysh[NC + cc0], c0 = ysh[2 * NC + cc0];
        yc0[0]=a0.x; yc0[1]=a0.y; yc0[2]=a0.z; yc0[3]=a0.w;
        yc0[4]=b0.x; yc0[5]=b0.y; yc0[6]=b0.z; yc0[7]=b0.w;
        yc0[8]=c0.x; yc0[9]=c0.y; yc0[10]=c0.z;
        uint4 a1 = ysh[cc1], b1 = ysh[NC + cc1], c1 = ysh[2 * NC + cc1];
        yc1[0]=a1.x; yc1[1]=a1.y; yc1[2]=a1.z; yc1[3]=a1.w;
        yc1[4]=b1.x; yc1[5]=b1.y; yc1[6]=b1.z; yc1[7]=b1.w;
        yc1[8]=c1.x; yc1[9]=c1.y; yc1[10]=c1.z;
    }
    // overwrite the center's ch21 flag with -1.0 (half 0xBC00): dot' = <y,y> - 1
    yc0[10] = (yc0[10] & 0x0000FFFFu) | 0xBC000000u;
    yc1[10] = (yc1[10] & 0x0000FFFFu) | 0xBC000000u;

    const float4 xc0 = Ash4[cc0];
    const float4 xc1 = Ash4[cc1];
    const u64 ng0 = pack2(-xc0.x, -xc1.x);
    const u64 ng1 = pack2(-xc0.y, -xc1.y);
    const u64 ng2 = pack2(-xc0.z, -xc1.z);

    u32 accP0 = 0u, accP1 = 0u;       // half2 accumulators of K*dot'
    const uint2* tabg = TABH + g * 36;
    const int rbase = py * HLW + g * 13 + px;

    // ---- software-pipelined mainloop over 36 cells (R9 skeleton) ----
    float4 xv  = Ash4[rbase];
    uint4  v0  = ysh[rbase];
    uint4  v1  = ysh[NC + rbase];
    uint4  v2  = ysh[2 * NC + rbase];
    uint2  tp  = tabg[0];

    #pragma unroll
    for (int idx = 0; idx < 36; ++idx) {
        const float4 cxv = xv;
        const uint4 cv0 = v0, cv1 = v1, cv2 = v2;
        const uint2 ctp = tp;
        if (idx < 35) {
            const int ni = idx + 1;
            const int ncell = rbase + (ni / 6) * HLW + (ni % 6);
            xv = Ash4[ncell];
            v0 = ysh[ncell];
            v1 = ysh[NC + ncell];
            v2 = ysh[2 * NC + ncell];
            tp = tabg[ni];
        }

        // sp = 50*log2e*|x_q - x_p|^2, packed over (pc0,pc1)
        u64 d0 = add2(pack2(cxv.x, cxv.x), ng0);
        u64 d1 = add2(pack2(cxv.y, cxv.y), ng1);
        u64 d2 = add2(pack2(cxv.z, cxv.z), ng2);
        u64 sp = mul2(d0, d0); sp = ffma2(d1, d1, sp); sp = ffma2(d2, d2, sp);
        float s0, s1; unpack2(sp, s0, s1);
        // fp16 exp + K-combine: E = 2^-s (both pixels), K = E*0.9t + 0.1t
        __half2 sh = __floats2half2_rn(s0, s1);
        const u32 E = hex2((*(u32*)&sh) ^ SGN2);
        const u32 Kh = hfma2u(E, ctp.x, ctp.y);      // (K0, K1)
        const u32 Kd0 = prmt(Kh, 0x1010u);           // (K0, K0)
        const u32 Kd1 = prmt(Kh, 0x3232u);           // (K1, K1)

        // dot' chains: 11 half2 terms per pixel, split 6+5
        u32 dp0a = hmul2u(cv0.x, yc0[0]);
        u32 dp1a = hmul2u(cv0.x, yc1[0]);
        u32 dp0b = hmul2u(cv1.z, yc0[6]);
        u32 dp1b = hmul2u(cv1.z, yc1[6]);
        dp0a = hfma2u(cv0.y, yc0[1], dp0a);  dp1a = hfma2u(cv0.y, yc1[1], dp1a);
        dp0b = hfma2u(cv1.w, yc0[7], dp0b);  dp1b = hfma2u(cv1.w, yc1[7], dp1b);
        dp0a = hfma2u(cv0.z, yc0[2], dp0a);  dp1a = hfma2u(cv0.z, yc1[2], dp1a);
        dp0b = hfma2u(cv2.x, yc0[8], dp0b);  dp1b = hfma2u(cv2.x, yc1[8], dp1b);
        dp0a = hfma2u(cv0.w, yc0[3], dp0a);  dp1a = hfma2u(cv0.w, yc1[3], dp1a);
        dp0b = hfma2u(cv2.y, yc0[9], dp0b);  dp1b = hfma2u(cv2.y, yc1[9], dp1b);
        dp0a = hfma2u(cv1.x, yc0[4], dp0a);  dp1a = hfma2u(cv1.x, yc1[4], dp1a);
        dp0b = hfma2u(cv2.z, yc0[10], dp0b); dp1b = hfma2u(cv2.z, yc1[10], dp1b);
        dp0a = hfma2u(cv1.y, yc0[5], dp0a);  dp1a = hfma2u(cv1.y, yc1[5], dp1a);
        const u32 dp0 = hadd2u(dp0a, dp0b);
        const u32 dp1 = hadd2u(dp1a, dp1b);

        accP0 = hfma2u(Kd0, dp0, accP0);
        accP1 = hfma2u(Kd1, dp1, accP1);
    }

    // ---- epilogue: part = -sum(K*dot') + true-OOB closed form ----
    float acc2;
    {
        __half2 a = *(__half2*)&accP0;
        __half2 b = *(__half2*)&accP1;
        acc2 = (__low2float(a) + __high2float(a)) + (__low2float(b) + __high2float(b));
    }
    float acc1 = 0.0f;
    if (g == 0) {
        const int h = th0 + py;
        const int rv = min(5, 127 - h) + min(5, h) + 1;
        #pragma unroll
        for (int pc = 0; pc < 2; ++pc) {
            const int w = tw0 + 2 * px + pc;
            const int cv = min(5, 127 - w) + min(5, w) + 1;
            const int noob = 121 - rv * cv;
            if (noob > 0) {
                const float4 xc = pc ? xc1 : xc0;
                const float sxs = xc.x * xc.x + xc.y * xc.y + xc.z * xc.z;  // scaled
                const float F = fmaf(0.9f, ex2(-sxs), 0.1f);
                acc1 += (float)noob * ex2((float)(h * h + w * w) * CXY) * F;
            }
        }
    }

    // ---- block reduction + fused final reduction (deterministic) ----
    float part = acc1 - acc2;
    #pragma unroll
    for (int o = 16; o > 0; o >>= 1) part += __shfl_xor_sync(0xffffffffu, part, o);
    const int warp = tid >> 5, lane = tid & 31;
    if (lane == 0) red[warp] = part;
    __syncthreads();
    const int bid = ((bz * gridDim.y) + blockIdx.y) * gridDim.x + blockIdx.x;
    if (tid == 0) {
        g_part[bid] = (red[0] + red[1]) + (red[2] + red[3]);
        __threadfence();
        unsigned old = atomicAdd(&g_cnt, 1u);
        lastflag = (old == NBLK - 1) ? 1 : 0;
    }
    __syncthreads();
    if (lastflag) {
        float v = (g_part[tid] + g_part[tid + 128]) +
                  (g_part[tid + 256] + g_part[tid + 384]);
        #pragma unroll
        for (int o = 16; o > 0; o >>= 1) v += __shfl_xor_sync(0xffffffffu, v, o);
        if (lane == 0) red[warp] = v;
        __syncthreads();
        if (tid == 0) {
            out[0] = ((red[0] + red[1]) + (red[2] + red[3])) * (1.0f / 65536.0f);
            g_cnt = 0;
        }
    }
}

extern "C" void kernel_launch(void* const* d_in, const int* in_sizes, int n_in,
                              void* d_out, int out_size) {
    const float* x = (const float*)d_in[0];
    const float* y = (const float*)d_in[1];
    (void)in_sizes; (void)n_in; (void)out_size;
    dim3 grid(WW / TW, HH / TH, 4);
    crf_fused<<<grid, NT>>>(x, y, (float*)d_out);
}